// round 3
// baseline (speedup 1.0000x reference)
#include <cuda_runtime.h>
#include <cstddef>

// Problem constants
#define DN      32          // feature dim
#define DS      36          // padded shared row stride (floats)
#define ITEM    33          // stored item row length: 32 matrix cols + v
#define L_LAYERS 10000
#define NCHUNK  296         // 2 blocks per SM on 148 SMs
#define LVL1    37          // 296 / 8
#define LVL2    5           // ceil(37/8)

// Scratch (allocation-free: __device__ globals)
__device__ float g_it0[NCHUNK * 32 * ITEM];
__device__ float g_it1[LVL1 * 32 * ITEM];
__device__ float g_it2[LVL2 * 32 * ITEM];
__device__ float g_fin[32 * ITEM];
__device__ float g_P[2048 * 32];
__device__ int   g_flag;

// One affine composition step:
//   Uo[c][j] = sum_k L[c][k] * U[k][j]          (j = 0..31, the matrix part)
//   Uo[c][32] = sum_k L[c][k] * U[k][32] + L[c][32]   (the bias column)
// Threads 0..255: (c = t>>3, j0 = (t&7)*4) compute a float4 of the matrix.
// Threads 256..287 (warp 8): lane cc computes the bias column entry.
__device__ __forceinline__ void affine_step(
    const float (*U)[DS], const float (*Wb)[DS], float (*Uo)[DS], int t)
{
    if (t < 256) {
        const int c  = t >> 3;
        const int j0 = (t & 7) * 4;
        float lrow[32];
#pragma unroll
        for (int q = 0; q < 8; ++q) {
            float4 v4 = *(const float4*)&Wb[c][4 * q];
            lrow[4 * q + 0] = v4.x; lrow[4 * q + 1] = v4.y;
            lrow[4 * q + 2] = v4.z; lrow[4 * q + 3] = v4.w;
        }
        float a0 = 0.f, a1 = 0.f, a2 = 0.f, a3 = 0.f;
#pragma unroll
        for (int k = 0; k < 32; ++k) {
            float4 u = *(const float4*)&U[k][j0];
            a0 = fmaf(lrow[k], u.x, a0);
            a1 = fmaf(lrow[k], u.y, a1);
            a2 = fmaf(lrow[k], u.z, a2);
            a3 = fmaf(lrow[k], u.w, a3);
        }
        *(float4*)&Uo[c][j0] = make_float4(a0, a1, a2, a3);
    } else {
        const int cc = t - 256;
        float acc = Wb[cc][32];
#pragma unroll
        for (int k = 0; k < 32; ++k)
            acc = fmaf(Wb[cc][k], U[k][32], acc);
        Uo[cc][32] = acc;
    }
}

// Stage 1: each block composes a contiguous chunk of layers sequentially.
// Layer i contributes L = W_i (natural layout) and bias b_i in col 32.
__global__ __launch_bounds__(288) void k_chunk(
    const float* __restrict__ W, const float* __restrict__ b,
    float* __restrict__ out)
{
    __shared__ float sU[2][32][DS];
    __shared__ float sW[2][32][DS];
    const int t   = threadIdx.x;
    const int blk = blockIdx.x;
    // 10000 = 232*34 + 64*33
    const int start = blk * 33 + (blk < 232 ? blk : 232);
    const int len   = 33 + (blk < 232 ? 1 : 0);
    const int end   = start + len;

    // U := identity, v := 0
    for (int idx = t; idx < 32 * DS; idx += 288) {
        int r = idx / DS, q = idx % DS;
        sU[0][r][q] = (q == r) ? 1.0f : 0.0f;
    }

    // Prefetch first layer into registers
    float4 wreg = make_float4(0.f, 0.f, 0.f, 0.f);
    float  breg = 0.f;
    if (t < 256) wreg = *(const float4*)(W + (size_t)start * 1024 + t * 4);
    else         breg = b[start * 32 + (t - 256)];

    int p = 0;
    for (int i = start; i < end; ++i, p ^= 1) {
        if (t < 256) {
            int c = t >> 3, j0 = (t & 7) * 4;
            *(float4*)&sW[p][c][j0] = wreg;
        } else {
            sW[p][t - 256][32] = breg;
        }
        __syncthreads();   // single barrier per layer (double-buffered hazards checked)
        if (i + 1 < end) { // prefetch next layer while computing this one
            if (t < 256) wreg = *(const float4*)(W + (size_t)(i + 1) * 1024 + t * 4);
            else         breg = b[(i + 1) * 32 + (t - 256)];
        }
        affine_step(sU[p], sW[p], sU[p ^ 1], t);
    }
    __syncthreads();

    float* dst = out + (size_t)blk * (32 * ITEM);
    for (int idx = t; idx < 32 * ITEM; idx += 288)
        dst[idx] = sU[p][idx / ITEM][idx % ITEM];
}

// Tree combine: each block sequentially composes `group` consecutive stored
// items (earliest first). Item q acts as the "later" operand L.
__global__ __launch_bounds__(288) void k_combine(
    const float* __restrict__ in, float* __restrict__ out,
    int group, int total, int resetFlag)
{
    __shared__ float sU[2][32][DS];
    __shared__ float sW[2][32][DS];
    const int t   = threadIdx.x;
    const int blk = blockIdx.x;
    const int startItem = blk * group;
    const int n = min(group, total - startItem);

    if (resetFlag && blk == 0 && t == 0) g_flag = 0;

    const float* first = in + (size_t)startItem * (32 * ITEM);
    for (int idx = t; idx < 32 * ITEM; idx += 288)
        sU[0][idx / ITEM][idx % ITEM] = first[idx];

    float w0 = 0.f, w1 = 0.f, w2 = 0.f, w3 = 0.f, breg = 0.f;
    int c = 0, j0 = 0;
    if (t < 256) { c = t >> 3; j0 = (t & 7) * 4; }

    if (n > 1) {
        const float* it = in + (size_t)(startItem + 1) * (32 * ITEM);
        if (t < 256) {
            w0 = it[c * ITEM + j0 + 0]; w1 = it[c * ITEM + j0 + 1];
            w2 = it[c * ITEM + j0 + 2]; w3 = it[c * ITEM + j0 + 3];
        } else {
            breg = it[(t - 256) * ITEM + 32];
        }
    }

    int p = 0;
    for (int q = 1; q < n; ++q, p ^= 1) {
        if (t < 256) {
            sW[p][c][j0 + 0] = w0; sW[p][c][j0 + 1] = w1;
            sW[p][c][j0 + 2] = w2; sW[p][c][j0 + 3] = w3;
        } else {
            sW[p][t - 256][32] = breg;
        }
        __syncthreads();
        if (q + 1 < n) {
            const float* it = in + (size_t)(startItem + q + 1) * (32 * ITEM);
            if (t < 256) {
                w0 = it[c * ITEM + j0 + 0]; w1 = it[c * ITEM + j0 + 1];
                w2 = it[c * ITEM + j0 + 2]; w3 = it[c * ITEM + j0 + 3];
            } else {
                breg = it[(t - 256) * ITEM + 32];
            }
        }
        affine_step(sU[p], sW[p], sU[p ^ 1], t);
    }
    __syncthreads();

    float* dst = out + (size_t)blk * (32 * ITEM);
    for (int idx = t; idx < 32 * ITEM; idx += 288)
        dst[idx] = sU[p][idx / ITEM][idx % ITEM];
}

// P = (y+z) @ M, where M[k][d] = U[d][k]. Sets g_flag if any P entry != 0.
__global__ void k_P(const float* __restrict__ y, const float* __restrict__ z)
{
    __shared__ float shU[32 * ITEM];
    const int t = threadIdx.x;
    for (int idx = t; idx < 32 * ITEM; idx += 256) shU[idx] = g_fin[idx];
    __syncthreads();

    const int gid = blockIdx.x * 256 + t;   // 2048*32 outputs
    const int e = gid >> 5, d = gid & 31;
    const float* yr = y + e * 32;
    const float* zr = z + e * 32;
    float acc = 0.f;
#pragma unroll
    for (int m = 0; m < 32; ++m)
        acc = fmaf(yr[m] + zr[m], shU[d * ITEM + m], acc);
    g_P[gid] = acc;
    if (acc != 0.0f) atomicOr(&g_flag, 1);
}

// out[row][d] = v[d]                         if P == 0 exactly (bit-equal fast path)
//             = sum_m x[row][m]*P[m][d]+v[d] otherwise
__global__ void k_out(const float* __restrict__ x, float* __restrict__ out)
{
    __shared__ float shv[32];
    __shared__ int   sflag;
    const int t = threadIdx.x;
    if (t < 32) shv[t] = g_fin[t * ITEM + 32];
    if (t == 0) sflag = g_flag;
    __syncthreads();

    const int gid = blockIdx.x * 256 + t;   // 1024*32 outputs
    const int row = gid >> 5, d = gid & 31;
    if (!sflag) { out[gid] = shv[d]; return; }

    const float* xr = x + (size_t)row * 2048;
    float acc = shv[d];
#pragma unroll 4
    for (int m = 0; m < 2048; m += 4) {
        float4 xv = *(const float4*)(xr + m);
        acc = fmaf(xv.x, g_P[(m + 0) * 32 + d], acc);
        acc = fmaf(xv.y, g_P[(m + 1) * 32 + d], acc);
        acc = fmaf(xv.z, g_P[(m + 2) * 32 + d], acc);
        acc = fmaf(xv.w, g_P[(m + 3) * 32 + d], acc);
    }
    out[gid] = acc;
}

extern "C" void kernel_launch(void* const* d_in, const int* in_sizes, int n_in,
                              void* d_out, int out_size)
{
    // Bind inputs by element count (robust to ordering):
    //  x: 1024*2048=2097152, y/z: 65536 (symmetric: only y+z used),
    //  W: 10000*32*32=10240000, b: 10000*32=320000
    const float *x = nullptr, *y = nullptr, *z = nullptr, *W = nullptr, *b = nullptr;
    for (int i = 0; i < n_in; ++i) {
        const float* p = (const float*)d_in[i];
        switch (in_sizes[i]) {
            case 2097152:  x = p; break;
            case 10240000: W = p; break;
            case 320000:   b = p; break;
            case 65536:    if (!y) y = p; else z = p; break;
            default: break;
        }
    }
    float* out = (float*)d_out;

    float *it0, *it1, *it2, *fin;
    cudaGetSymbolAddress((void**)&it0, g_it0);
    cudaGetSymbolAddress((void**)&it1, g_it1);
    cudaGetSymbolAddress((void**)&it2, g_it2);
    cudaGetSymbolAddress((void**)&fin, g_fin);

    k_chunk  <<<NCHUNK, 288>>>(W, b, it0);
    k_combine<<<LVL1,   288>>>(it0, it1, 8,    NCHUNK, 0);
    k_combine<<<LVL2,   288>>>(it1, it2, 8,    LVL1,   0);
    k_combine<<<1,      288>>>(it2, fin, LVL2, LVL2,   1);
    k_P      <<<256,    256>>>(y, z);
    k_out    <<<128,    256>>>(x, out);
}